// round 17
// baseline (speedup 1.0000x reference)
#include <cuda_runtime.h>
#include <cstdint>
#include <cstdio>

#define B_   256
#define T_   600
#define I_   129
#define H_   200
#define G_   800   // 4*H
#define KP_  160   // padded K for the I=129 operands
#define HPW_ 104   // packed bf16 h row: 13 kb2-groups * 8 uint32 words
#define XPW_ 80    // packed bf16 xt row: 10 kb2-groups * 8 words

// wave-role smem word offsets
#define OFF_WHH  0        // 32*104
#define OFF_WIH2 3328     // 32*104
#define OFF_WIH1 6656     // 32*88 (stride 88, 80 used)
#define OFF_H    9472     // 128*104
#define OFF_XT   22784    // 128*88
#define OFF_GS   34048    // 128*40 floats
// FC-role layout: [0, 2*TB2) staging, y1 at 2*TB2 (128*164 floats)
#define TB2      9216
#define OFF_Y1   18432
#define SMEM_WORDS 39424  // max(wave 39168, fc 39424) -> 157696 B

// ---------------- scratch (device globals; no cudaMalloc allowed) ----------------
__device__ float    g_xg2[(size_t)T_ * B_ * G_];     // xg2 (with biases, from L1)
__device__ unsigned g_xtb[(size_t)T_ * B_ * XPW_];   // packed bf16 xt
__device__ unsigned g_hs1[(size_t)T_ * B_ * HPW_];   // packed bf16 h, layer 1
__device__ unsigned g_hs2[(size_t)T_ * B_ * HPW_];   // packed bf16 h, layer 2
__device__ float    g_h2l[(size_t)T_ * B_ * H_];     // linear fp32 h2 (for fc)
__device__ float    g_wp2[I_ * KP_];                 // fc2_w padded to [129,160]

// single end-of-kernel drain barrier (all blocks)
__device__ unsigned g_cnt = 0;
__device__ unsigned g_gen = 0;
// per-step arrival epochs: [barid][block]; value = completed step + 1
__device__ unsigned g_arr[4][25];
// L1 -> L2 progress flags (completed L1 xg2 step)
__device__ unsigned g_l1prog[2][25];

// ---------------- fast activations ----------------
__device__ __forceinline__ float sigmf(float x) {
    return __fdividef(1.f, 1.f + __expf(-x));
}
__device__ __forceinline__ float tanh_fast(float x) {
    float e = __expf(2.f * x);
    return 1.f - __fdividef(2.f, e + 1.f);
}

// ---------------- tf32 / bf16 helpers ----------------
__device__ __forceinline__ uint32_t f2tf32(float x) {
    uint32_t r;
    asm("cvt.rna.tf32.f32 %0, %1;" : "=r"(r) : "f"(x));
    return r;
}
__device__ __forceinline__ float tfhi(float v) { return __uint_as_float(f2tf32(v)); }
__device__ __forceinline__ uint32_t fu(float v) { return __float_as_uint(v); }

__device__ __forceinline__ uint32_t bf2(float a, float b) {
    uint32_t r;
    asm("cvt.rn.bf16x2.f32 %0, %1, %2;" : "=r"(r) : "f"(b), "f"(a));
    return r;
}

__device__ __forceinline__ void st_release_gpu(unsigned* p, unsigned v) {
    asm volatile("st.release.gpu.u32 [%0], %1;" :: "l"(p), "r"(v) : "memory");
}
__device__ __forceinline__ unsigned ld_acquire_gpu(const unsigned* p) {
    unsigned v;
    asm volatile("ld.acquire.gpu.u32 %0, [%1];" : "=r"(v) : "l"(p) : "memory");
    return v;
}

__device__ __forceinline__ void mma_tf32(float* d, const uint32_t* a, const uint32_t* b) {
    asm volatile(
        "mma.sync.aligned.m16n8k8.row.col.f32.tf32.tf32.f32 "
        "{%0,%1,%2,%3}, {%4,%5,%6,%7}, {%8,%9}, {%0,%1,%2,%3};"
        : "+f"(d[0]), "+f"(d[1]), "+f"(d[2]), "+f"(d[3])
        : "r"(a[0]), "r"(a[1]), "r"(a[2]), "r"(a[3]), "r"(b[0]), "r"(b[1]));
}
__device__ __forceinline__ void mma_bf16(float* d, const uint32_t* a, const uint32_t* b) {
    asm volatile(
        "mma.sync.aligned.m16n8k16.row.col.f32.bf16.bf16.f32 "
        "{%0,%1,%2,%3}, {%4,%5,%6,%7}, {%8,%9}, {%0,%1,%2,%3};"
        : "+f"(d[0]), "+f"(d[1]), "+f"(d[2]), "+f"(d[3])
        : "r"(a[0]), "r"(a[1]), "r"(a[2]), "r"(a[3]), "r"(b[0]), "r"(b[1]));
}

__device__ __forceinline__ void cpasync16(uint32_t dst, const void* src) {
    asm volatile("cp.async.cg.shared.global [%0], [%1], 16;" :: "r"(dst), "l"(src));
}

// interleaved 8-k split for the 3xTF32 FC GEMMs
__device__ __forceinline__ void split8(float4 p0, float4 p1, float4 q[4])
{
    float h0 = tfhi(p0.x), h1 = tfhi(p0.y), h2 = tfhi(p0.z), h3 = tfhi(p0.w);
    float g0 = tfhi(p1.x), g1 = tfhi(p1.y), g2 = tfhi(p1.z), g3 = tfhi(p1.w);
    q[0] = make_float4(h0, g0, tfhi(p0.x - h0), tfhi(p1.x - g0));
    q[1] = make_float4(h1, g1, tfhi(p0.y - h1), tfhi(p1.y - g1));
    q[2] = make_float4(h2, g2, tfhi(p0.z - h2), tfhi(p1.z - g2));
    q[3] = make_float4(h3, g3, tfhi(p0.w - h3), tfhi(p1.w - g3));
}

// ---------------- weight padding ----------------
__global__ void pad_w(const float* __restrict__ w, float* __restrict__ wp, int N, int K)
{
    int i = blockIdx.x * 256 + threadIdx.x;
    if (i < N * KP_) {
        int n = i / KP_, k = i - n * KP_;
        wp[i] = (k < K) ? w[(size_t)n * K + k] : 0.f;
    }
}

// ---------------- fused transpose + bf16 pack: x[B,129,T] -> xtb words ----------
__global__ void transpose_pack(const float* __restrict__ x, unsigned* __restrict__ xtb)
{
    __shared__ float sm[32][33];
    const int b  = blockIdx.z;
    const int i0 = blockIdx.y * 32;
    const int t0 = blockIdx.x * 32;
    const int tx = threadIdx.x, ty = threadIdx.y;   // (32,8)
#pragma unroll
    for (int s = 0; s < 32; s += 8) {
        int i = i0 + ty + s, t = t0 + tx;
        sm[ty + s][tx] = (i < I_ && t < T_) ? x[((size_t)b * I_ + i) * T_ + t] : 0.f;
    }
    __syncthreads();
#pragma unroll
    for (int j = 0; j < 2; ++j) {
        int widx = (ty * 32 + tx) + 256 * j;        // 0..511
        int tl = widx >> 4, rem16 = widx & 15;
        int kb2l = rem16 >> 3, w = rem16 & 7;
        int kl = (w & 1) ? (w + 7) : w;             // pair-interleaved layout
        int il = kb2l * 16 + kl;
        int t = t0 + tl;
        if (t < T_) {
            unsigned v = bf2(sm[il][tl], sm[il + 1][tl]);
            xtb[((size_t)t * B_ + b) * XPW_ + (i0 >> 4) * 8 + kb2l * 8 + w] = v;
        }
    }
}

// ---------------- 3xTF32 GEMM building blocks (FC role) --------------------------
__device__ __forceinline__ void ld_regs(
    const float* __restrict__ A, int ldA,
    const float* __restrict__ W, int ldW,
    int m0, int n0, int N, int K, int kt, int tid,
    float4 ra[2], float4 rw[2])
{
    const float4 z = make_float4(0.f, 0.f, 0.f, 0.f);
    const int row = tid >> 1, kbl = tid & 1;
    int k = kt * 16 + kbl * 8;
    if (k + 8 <= K) {
        const float* p = A + (size_t)(m0 + row) * ldA + k;
        ra[0] = *(const float4*)p;
        ra[1] = *(const float4*)(p + 4);
    } else { ra[0] = z; ra[1] = z; }
    if (tid < 128) {
        int wr = tid >> 1;
        if (k + 8 <= K && n0 + wr < N) {
            const float* p = W + (size_t)(n0 + wr) * ldW + k;
            rw[0] = *(const float4*)p;
            rw[1] = *(const float4*)(p + 4);
        } else { rw[0] = z; rw[1] = z; }
    }
}

__device__ __forceinline__ void ld_regs_y1(
    const float* __restrict__ y1s, const float* __restrict__ W,
    int n0, int kt, int tid, float4 ra[2], float4 rw[2])
{
    const float4 z = make_float4(0.f, 0.f, 0.f, 0.f);
    const int row = tid >> 1, kbl = tid & 1;
    int k = kt * 16 + kbl * 8;
    const float* p = y1s + row * 164 + k;
    ra[0] = *(const float4*)p;
    ra[1] = *(const float4*)(p + 4);
    if (tid < 128) {
        int wr = tid >> 1;
        if (n0 + wr < I_) {
            const float* q = W + (size_t)(n0 + wr) * KP_ + k;
            rw[0] = *(const float4*)q;
            rw[1] = *(const float4*)(q + 4);
        } else { rw[0] = z; rw[1] = z; }
    }
}

__device__ __forceinline__ void st_smem(float* buf, int tid, float4 ra[2], float4 rw[2])
{
    const int row = tid >> 1, kbl = tid & 1;
    {
        float4 q[4];
        split8(ra[0], ra[1], q);
        float4* da = (float4*)(buf + row * 48 + kbl * 16);
        int rot = row & 3;
#pragma unroll
        for (int j = 0; j < 4; ++j) { int jj = (rot + j) & 3; da[jj] = q[jj]; }
    }
    if (tid < 128) {
        int wr = tid >> 1;
        float4 q[4];
        split8(rw[0], rw[1], q);
        float4* dw = (float4*)(buf + 6144 + wr * 48 + kbl * 16);
        int rot = wr & 3;
#pragma unroll
        for (int j = 0; j < 4; ++j) { int jj = (rot + j) & 3; dw[jj] = q[jj]; }
    }
}

__device__ __forceinline__ void mma_tile16(const float* buf, int wm, int wn,
                                           int g4, int tg, float acc[2][4][4])
{
    const float* Sw = buf + 6144;
#pragma unroll
    for (int kk = 0; kk < 2; ++kk) {
        int koff = kk * 16 + tg * 4;
        uint32_t ah[2][4], al[2][4];
#pragma unroll
        for (int mf = 0; mf < 2; ++mf) {
            const float* pa = buf + (wm * 32 + mf * 16 + g4) * 48 + koff;
            float4 A0 = *(const float4*)pa;
            float4 A1 = *(const float4*)(pa + 8 * 48);
            ah[mf][0] = fu(A0.x); ah[mf][1] = fu(A1.x);
            ah[mf][2] = fu(A0.y); ah[mf][3] = fu(A1.y);
            al[mf][0] = fu(A0.z); al[mf][1] = fu(A1.z);
            al[mf][2] = fu(A0.w); al[mf][3] = fu(A1.w);
        }
#pragma unroll
        for (int nf = 0; nf < 4; ++nf) {
            const float* pb = Sw + (wn * 32 + nf * 8 + g4) * 48 + koff;
            float4 Bv = *(const float4*)pb;
            uint32_t bh[2] = {fu(Bv.x), fu(Bv.y)};
            uint32_t bl[2] = {fu(Bv.z), fu(Bv.w)};
            mma_tf32(acc[0][nf], ah[0], bh);
            mma_tf32(acc[0][nf], ah[0], bl);
            mma_tf32(acc[0][nf], al[0], bh);
            mma_tf32(acc[1][nf], ah[1], bh);
            mma_tf32(acc[1][nf], ah[1], bl);
            mma_tf32(acc[1][nf], al[1], bh);
        }
    }
}

// ---------------- unified persistent kernel --------------------------------------
// grid 148: [0,50) L1 wave, [50,100) L2 wave, [100,148) FC consumers.
// L1 main loop computes BOTH h@whh (acc) and h@wih2 (xac) per kb2, reusing the
// A fragments (halves deferred-section LDS). Deferred section = xg2 stores only.
__global__ void __launch_bounds__(256, 1) lstm_fused(
    const unsigned* __restrict__ xtb,
    const float* __restrict__ wih1, const float* __restrict__ bi1,
    const float* __restrict__ bh1,  const float* __restrict__ whh1,
    const float* __restrict__ wih2, const float* __restrict__ whh2,
    const float* __restrict__ bi2,  const float* __restrict__ bh2,
    unsigned* __restrict__ hs1, unsigned* __restrict__ hs2,
    float* __restrict__ h2l, float* __restrict__ xg2,
    const float* __restrict__ fc1_w, const float* __restrict__ fc1_b,
    const float* __restrict__ wp2,   const float* __restrict__ fc2_b,
    float* __restrict__ out)
{
    extern __shared__ uint32_t smu[];
    const int tid  = threadIdx.x;
    const int warp = tid >> 5, lane = tid & 31;
    const int g4 = lane >> 2, tg = lane & 3;
    const int wm = warp >> 1;
    const int wn = warp & 1;

    const int bx = blockIdx.x;
    const bool fcrole = (bx >= 100);
    int barid = 0, ublk = 0, isL2 = 0;

    if (fcrole) {
        // ================= FC role =================
        float* smf = (float*)smu;
        float* y1s = smf + OFF_Y1;          // 128 x 164
        const int fcid = bx - 100;          // 0..47

        for (int it = fcid; it < 2 * T_; it += 48) {
            const int t   = it >> 1;
            const int grp = it & 1;
            const int r0  = t * B_ + grp * 128;

            // low-contention wait: ONE thread, sequential flags, heavy backoff
            if (tid == 0) {
                for (int j = 0; j < 25; ++j) {
                    const unsigned* f = &g_arr[2 + grp][j];
                    while (ld_acquire_gpu(f) < (unsigned)(t + 1)) { __nanosleep(1024); }
                }
            }
            __syncthreads();

            float4 ra[2], rw[2];
            // ---- fc1: y1 = relu(h2 @ fc1_w^T + b1), cols 129..159 zero ----
#pragma unroll 1
            for (int nt = 0; nt < 3; ++nt) {
                int n0 = nt * 64;
                float acc[2][4][4] = {};
                ld_regs(h2l, H_, fc1_w, H_, r0, n0, I_, H_, 0, tid, ra, rw);
                st_smem(smf, tid, ra, rw);
                __syncthreads();
#pragma unroll 1
                for (int kt = 0; kt < 13; ++kt) {
                    if (kt + 1 < 13)
                        ld_regs(h2l, H_, fc1_w, H_, r0, n0, I_, H_, kt + 1, tid, ra, rw);
                    mma_tile16(smf + (kt & 1) * TB2, wm, wn, g4, tg, acc);
                    if (kt + 1 < 13)
                        st_smem(smf + ((kt + 1) & 1) * TB2, tid, ra, rw);
                    __syncthreads();
                }
#pragma unroll
                for (int mf = 0; mf < 2; ++mf) {
                    int m_a = wm * 32 + mf * 16 + g4;
#pragma unroll
                    for (int nf = 0; nf < 4; ++nf) {
                        int n = n0 + wn * 32 + nf * 8 + tg * 2;
#pragma unroll
                        for (int half = 0; half < 2; ++half) {
                            int m = m_a + half * 8;
                            if (n < KP_) {
                                float v0 = acc[mf][nf][half * 2 + 0];
                                float v1 = acc[mf][nf][half * 2 + 1];
                                y1s[m * 164 + n]     = (n     < I_) ? fmaxf(v0 + fc1_b[n], 0.f)     : 0.f;
                                y1s[m * 164 + n + 1] = (n + 1 < I_) ? fmaxf(v1 + fc1_b[n + 1], 0.f) : 0.f;
                            }
                        }
                    }
                }
                __syncthreads();
            }

            // ---- fc2: out = sigmoid(y1 @ wp2^T + b2), transposed [B,129,T] ----
#pragma unroll 1
            for (int nt = 0; nt < 3; ++nt) {
                int n0 = nt * 64;
                float acc[2][4][4] = {};
                ld_regs_y1(y1s, wp2, n0, 0, tid, ra, rw);
                st_smem(smf, tid, ra, rw);
                __syncthreads();
#pragma unroll 1
                for (int kt = 0; kt < 10; ++kt) {
                    if (kt + 1 < 10)
                        ld_regs_y1(y1s, wp2, n0, kt + 1, tid, ra, rw);
                    mma_tile16(smf + (kt & 1) * TB2, wm, wn, g4, tg, acc);
                    if (kt + 1 < 10)
                        st_smem(smf + ((kt + 1) & 1) * TB2, tid, ra, rw);
                    __syncthreads();
                }
#pragma unroll
                for (int mf = 0; mf < 2; ++mf) {
                    int m_a = wm * 32 + mf * 16 + g4;
#pragma unroll
                    for (int nf = 0; nf < 4; ++nf) {
                        int n = n0 + wn * 32 + nf * 8 + tg * 2;
#pragma unroll
                        for (int half = 0; half < 2; ++half) {
                            int m = m_a + half * 8;
                            int b = grp * 128 + m;
                            float v0 = acc[mf][nf][half * 2 + 0];
                            float v1 = acc[mf][nf][half * 2 + 1];
                            if (n < I_)
                                out[((size_t)b * I_ + n) * T_ + t] = sigmf(v0 + fc2_b[n]);
                            if (n + 1 < I_)
                                out[((size_t)b * I_ + n + 1) * T_ + t] = sigmf(v1 + fc2_b[n + 1]);
                        }
                    }
                }
                __syncthreads();
            }
        }
    } else {
        // ================= wave roles (L1/L2) =================
        uint32_t* w_su  = smu + OFF_WHH;
        uint32_t* w2_su = smu + OFF_WIH2;
        uint32_t* w1_su = smu + OFF_WIH1;
        uint32_t* h_su  = smu + OFF_H;
        uint32_t* xt_su = smu + OFF_XT;
        float*    g_s   = (float*)(smu + OFF_GS);

        const int role = (bx >= 50);
        isL2 = role;
        const int bid  = bx - role * 50;
        const int grp  = bid / 25;
        ublk = bid - grp * 25;
        const int gb0  = grp * 128;
        const int u0   = ublk * 8;
        barid = role * 2 + grp;

        const float* whh = role ? whh2 : whh1;
        unsigned* hsout = role ? hs2 : hs1;
        unsigned* flag = &g_l1prog[grp][ublk];

        for (int i = 0; i < 13; ++i) {
            int lin = tid + 256 * i;
            if (lin < 3328) {
                int c = lin / 104, rem = lin - c * 104;
                int kb2 = rem >> 3, w = rem & 7;
                int kl = (w & 1) ? (w + 7) : w;
                int k0 = kb2 * 16 + kl;
                int grow = (c >> 3) * H_ + u0 + (c & 7);
                const float* wr_ = whh + (size_t)grow * H_;
                float v0 = (k0     < H_) ? wr_[k0]     : 0.f;
                float v1 = (k0 + 1 < H_) ? wr_[k0 + 1] : 0.f;
                w_su[c * 104 + kb2 * 8 + w] = bf2(v0, v1);
                if (!role) {
                    const float* w2r = wih2 + (size_t)grow * H_;
                    float u0v = (k0     < H_) ? w2r[k0]     : 0.f;
                    float u1v = (k0 + 1 < H_) ? w2r[k0 + 1] : 0.f;
                    w2_su[c * 104 + kb2 * 8 + w] = bf2(u0v, u1v);
                }
            }
        }
        if (!role) {
            for (int i = 0; i < 10; ++i) {
                int lin = tid + 256 * i;
                if (lin < 2560) {
                    int c = lin / 80, rem = lin - c * 80;
                    int kb2 = rem >> 3, w = rem & 7;
                    int kl = (w & 1) ? (w + 7) : w;
                    int k0 = kb2 * 16 + kl;
                    int grow = (c >> 3) * H_ + u0 + (c & 7);
                    const float* w1r = wih1 + (size_t)grow * I_;
                    float v0 = (k0     < I_) ? w1r[k0]     : 0.f;
                    float v1 = (k0 + 1 < I_) ? w1r[k0 + 1] : 0.f;
                    w1_su[c * 88 + kb2 * 8 + w] = bf2(v0, v1);
                }
            }
        }

        const int nc0 = (wn * 2 + 0) * H_ + u0 + tg * 2;
        const int nc1 = (wn * 2 + 1) * H_ + u0 + tg * 2;
        float bf00 = 0.f, bf01 = 0.f, bf10 = 0.f, bf11 = 0.f;
        if (!role) {
            bf00 = bi2[nc0] + bh2[nc0];     bf01 = bi2[nc0 + 1] + bh2[nc0 + 1];
            bf10 = bi2[nc1] + bh2[nc1];     bf11 = bi2[nc1 + 1] + bh2[nc1 + 1];
        }

        const int eb  = tid >> 1;
        const int eul = (tid & 1) * 4;
        float cc0 = 0.f, cc1 = 0.f, cc2 = 0.f, cc3 = 0.f;
        const int ug = u0 + eul;
        const int jg = ug >> 4;
        const int rr = ug & 15;
        const int p0 = rr >> 1;
        const int wo0 = (p0     < 4) ? 2 * p0       : 2 * (p0 - 4) + 1;
        const int wo1 = (p0 + 1 < 4) ? 2 * (p0 + 1) : 2 * (p0 - 3) + 1;

        float4 bq0, bq1, bq2, bq3;
        if (!role) {
            const float* bA = bi1; const float* bB = bh1;
            bq0 = make_float4(bA[0*H_+ug]+bB[0*H_+ug], bA[0*H_+ug+1]+bB[0*H_+ug+1],
                              bA[0*H_+ug+2]+bB[0*H_+ug+2], bA[0*H_+ug+3]+bB[0*H_+ug+3]);
            bq1 = make_float4(bA[1*H_+ug]+bB[1*H_+ug], bA[1*H_+ug+1]+bB[1*H_+ug+1],
                              bA[1*H_+ug+2]+bB[1*H_+ug+2], bA[1*H_+ug+3]+bB[1*H_+ug+3]);
            bq2 = make_float4(bA[2*H_+ug]+bB[2*H_+ug], bA[2*H_+ug+1]+bB[2*H_+ug+1],
                              bA[2*H_+ug+2]+bB[2*H_+ug+2], bA[2*H_+ug+3]+bB[2*H_+ug+3]);
            bq3 = make_float4(bA[3*H_+ug]+bB[3*H_+ug], bA[3*H_+ug+1]+bB[3*H_+ug+1],
                              bA[3*H_+ug+2]+bB[3*H_+ug+2], bA[3*H_+ug+3]+bB[3*H_+ug+3]);
        }

        const uint32_t* hA  = h_su + (wm * 32 + g4) * 104 + tg * 2;
        const uint32_t* xA  = xt_su + (wm * 32 + g4) * 88 + tg * 2;
        const uint32_t* wB0 = w_su + (wn * 16 + g4) * 104 + tg * 2;
        const uint32_t* wB1 = wB0 + 8 * 104;
        const uint32_t* vB0 = w2_su + (wn * 16 + g4) * 104 + tg * 2;
        const uint32_t* vB1 = vB0 + 8 * 104;
        const uint32_t* uB0 = w1_su + (wn * 16 + g4) * 88 + tg * 2;
        const uint32_t* uB1 = uB0 + 8 * 88;
        const int rowM = gb0 + wm * 32 + g4;
        const uint32_t h_su32  = (uint32_t)__cvta_generic_to_shared(h_su);
        const uint32_t xt_su32 = (uint32_t)__cvta_generic_to_shared(xt_su);

        // L1: prefetch xt(0) before the loop
        if (!role) {
            const uint4* src = (const uint4*)(xtb + ((size_t)0 * B_ + gb0) * XPW_);
#pragma unroll
            for (int i = 0; i < 10; ++i) {
                int lin = tid + 256 * i;
                int row = lin / 20, rem = lin - row * 20;
                cpasync16(xt_su32 + (row * 88 + rem * 4) * 4, src + row * 20 + rem);
            }
            asm volatile("cp.async.commit_group;" ::: "memory");
        }

        const int TEND = role ? T_ : T_ + 1;

        for (int t = 0; t < TEND; ++t) {
            const bool tail = (!role && t == T_);

            if (t > 0) {
                if (warp == 0) {
                    if (lane < 25) {
                        const unsigned* f = &g_arr[barid][lane];
                        while (ld_acquire_gpu(f) < (unsigned)t) { __nanosleep(32); }
                    }
                    if (role && lane == 25) {
                        while (ld_acquire_gpu(flag) < (unsigned)(t + 1)) { __nanosleep(32); }
                    }
                }
                __syncthreads();
            } else if (role) {
                if (tid == 0) {
                    while (ld_acquire_gpu(flag) < 1u) { __nanosleep(32); }
                }
                __syncthreads();
            }

            float4 q0, q1, q2, q3;
            if (role) {
                const float* xr = xg2 + ((size_t)t * B_ + gb0 + eb) * G_ + u0 + eul;
                q0 = *(const float4*)(xr);
                q1 = *(const float4*)(xr + H_);
                q2 = *(const float4*)(xr + 2 * H_);
                q3 = *(const float4*)(xr + 3 * H_);
            } else {
                q0 = bq0; q1 = bq1; q2 = bq2; q3 = bq3;
            }

            if (t == 0) {
                uint4 z = make_uint4(0u, 0u, 0u, 0u);
                for (int lin = tid; lin < 3328; lin += 256)
                    ((uint4*)h_su)[lin] = z;
            } else {
                const uint4* src = (const uint4*)(hsout + ((size_t)(t - 1) * B_ + gb0) * HPW_);
#pragma unroll
                for (int i = 0; i < 13; ++i) {
                    int lin = tid + 256 * i;
                    int row = lin / 26, rem = lin - row * 26;
                    cpasync16(h_su32 + (row * 104 + rem * 4) * 4, src + row * 26 + rem);
                }
                asm volatile("cp.async.commit_group;" ::: "memory");
            }

            float acc[2][2][4] = {};
            float xac[2][2][4] = {};

            if (!role && !tail) {
                // wait for the xt group only (h may still be in flight)
                if (t == 0) { asm volatile("cp.async.wait_group 0;" ::: "memory"); }
                else        { asm volatile("cp.async.wait_group 1;" ::: "memory"); }
                __syncthreads();
#pragma unroll
                for (int kb2 = 0; kb2 < 10; ++kb2) {
                    uint2 r0 = *(const uint2*)(xA + kb2 * 8);
                    uint2 r1 = *(const uint2*)(xA + kb2 * 8 + 8 * 88);
                    uint2 r2 = *(const uint2*)(xA + kb2 * 8 + 16 * 88);
                    uint2 r3 = *(const uint2*)(xA + kb2 * 8 + 24 * 88);
                    uint32_t a0[4] = {r0.x, r1.x, r0.y, r1.y};
                    uint32_t a1[4] = {r2.x, r3.x, r2.y, r3.y};
                    uint2 bb0 = *(const uint2*)(uB0 + kb2 * 8);
                    uint2 bb1 = *(const uint2*)(uB1 + kb2 * 8);
                    uint32_t b0[2] = {bb0.x, bb0.y};
                    uint32_t b1[2] = {bb1.x, bb1.y};
                    mma_bf16(acc[0][0], a0, b0);
                    mma_bf16(acc[1][0], a1, b0);
                    mma_bf16(acc[0][1], a0, b1);
                    mma_bf16(acc[1][1], a1, b1);
                }
                asm volatile("cp.async.wait_group 0;" ::: "memory");
                __syncthreads();
            } else {
                asm volatile("cp.async.wait_group 0;" ::: "memory");
                __syncthreads();
            }

            if (tail) {
                // final xg2(T-1) from staged h(T-1)
#pragma unroll
                for (int kb2 = 0; kb2 < 13; ++kb2) {
                    uint2 r0 = *(const uint2*)(hA + kb2 * 8);
                    uint2 r1 = *(const uint2*)(hA + kb2 * 8 + 8 * 104);
                    uint2 r2 = *(const uint2*)(hA + kb2 * 8 + 16 * 104);
                    uint2 r3 = *(const uint2*)(hA + kb2 * 8 + 24 * 104);
                    uint32_t a0[4] = {r0.x, r1.x, r0.y, r1.y};
                    uint32_t a1[4] = {r2.x, r3.x, r2.y, r3.y};
                    uint2 vv0 = *(const uint2*)(vB0 + kb2 * 8);
                    uint2 vv1 = *(const uint2*)(vB1 + kb2 * 8);
                    uint32_t v0[2] = {vv0.x, vv0.y};
                    uint32_t v1[2] = {vv1.x, vv1.y};
                    mma_bf16(xac[0][0], a0, v0);
                    mma_bf16(xac[1][0], a1, v0);
                    mma_bf16(xac[0][1], a0, v1);
                    mma_bf16(xac[1][1], a1, v1);
                }
#pragma unroll
                for (int mf = 0; mf < 2; ++mf) {
                    float* xo = xg2 + ((size_t)(t - 1) * B_ + rowM + mf * 16) * G_;
                    __stcg((float2*)(xo + nc0),          make_float2(xac[mf][0][0] + bf00, xac[mf][0][1] + bf01));
                    __stcg((float2*)(xo + nc1),          make_float2(xac[mf][1][0] + bf10, xac[mf][1][1] + bf11));
                    __stcg((float2*)(xo + 8 * G_ + nc0), make_float2(xac[mf][0][2] + bf00, xac[mf][0][3] + bf01));
                    __stcg((float2*)(xo + 8 * G_ + nc1), make_float2(xac[mf][1][2] + bf10, xac[mf][1][3] + bf11));
                }
                __syncthreads();
                if (tid == 0) st_release_gpu(flag, (unsigned)t);
                break;
            }

            // recurrence (+ fused xg2 with A-fragment reuse for L1)
#pragma unroll
            for (int kb2 = 0; kb2 < 13; ++kb2) {
                uint2 r0 = *(const uint2*)(hA + kb2 * 8);
                uint2 r1 = *(const uint2*)(hA + kb2 * 8 + 8 * 104);
                uint2 r2 = *(const uint2*)(hA + kb2 * 8 + 16 * 104);
                uint2 r3 = *(const uint2*)(hA + kb2 * 8 + 24 * 104);
                uint32_t a0[4] = {r0.x, r1.x, r0.y, r1.y};
                uint32_t a1[4] = {r2.x, r3.x, r2.y, r3.y};
                uint2 bb0 = *(const uint2*)(wB0 + kb2 * 8);
                uint2 bb1 = *(const uint2*)(wB1 + kb2 * 8);
                uint32_t b0[2] = {bb0.x, bb0.y};
                uint32_t b1[2] = {bb1.x, bb1.y};
                mma_bf16(acc[0][0], a0, b0);
                mma_bf16(acc[1][0], a1, b0);
                mma_bf16(acc[0][1], a0, b1);
                mma_bf16(acc[1][1], a1, b1);
                if (!role) {
                    uint2 vv0 = *(const uint2*)(vB0 + kb2 * 8);
                    uint2 vv1 = *(const uint2*)(vB1 + kb2 * 8);
                    uint32_t v0[2] = {vv0.x, vv0.y};
                    uint32_t v1[2] = {vv1.x, vv1.y};
                    mma_bf16(xac[0][0], a0, v0);
                    mma_bf16(xac[1][0], a1, v0);
                    mma_bf16(xac[0][1], a0, v1);
                    mma_bf16(xac[1][1], a1, v1);
                }
            }

#pragma unroll
            for (int mf = 0; mf < 2; ++mf) {
                float* d0 = g_s + (wm * 32 + mf * 16 + g4) * 40 + wn * 16 + tg * 2;
                *(float2*)(d0)              = make_float2(acc[mf][0][0], acc[mf][0][1]);
                *(float2*)(d0 + 8)          = make_float2(acc[mf][1][0], acc[mf][1][1]);
                *(float2*)(d0 + 8 * 40)     = make_float2(acc[mf][0][2], acc[mf][0][3]);
                *(float2*)(d0 + 8 * 40 + 8) = make_float2(acc[mf][1][2], acc[mf][1][3]);
            }
            __syncthreads();

            {
                const float* gr = g_s + eb * 40 + eul;
                float iv, fv, gv, ov, h0, h1, h2, h3;
                iv = sigmf(gr[0] + q0.x);  fv = sigmf(gr[8] + q1.x);
                gv = tanh_fast(gr[16] + q2.x); ov = sigmf(gr[24] + q3.x);
                cc0 = fv * cc0 + iv * gv;  h0 = ov * tanh_fast(cc0);

                iv = sigmf(gr[1] + q0.y);  fv = sigmf(gr[9] + q1.y);
                gv = tanh_fast(gr[17] + q2.y); ov = sigmf(gr[25] + q3.y);
                cc1 = fv * cc1 + iv * gv;  h1 = ov * tanh_fast(cc1);

                iv = sigmf(gr[2] + q0.z);  fv = sigmf(gr[10] + q1.z);
                gv = tanh_fast(gr[18] + q2.z); ov = sigmf(gr[26] + q3.z);
                cc2 = fv * cc2 + iv * gv;  h2 = ov * tanh_fast(cc2);

                iv = sigmf(gr[3] + q0.w);  fv = sigmf(gr[11] + q1.w);
                gv = tanh_fast(gr[19] + q2.w); ov = sigmf(gr[27] + q3.w);
                cc3 = fv * cc3 + iv * gv;  h3 = ov * tanh_fast(cc3);

                unsigned* hb = hsout + ((size_t)t * B_ + gb0 + eb) * HPW_ + jg * 8;
                __stcg(hb + wo0, bf2(h0, h1));
                __stcg(hb + wo1, bf2(h2, h3));
                if (role) {
                    float* hl = h2l + ((size_t)t * B_ + gb0 + eb) * H_ + u0 + eul;
                    *(float4*)hl = make_float4(h0, h1, h2, h3);
                }
            }

            // publish arrival ASAP
            __syncthreads();
            if (tid == 0) st_release_gpu(&g_arr[barid][ublk], (unsigned)(t + 1));

            // L1: prefetch xt(t+1) NOW so it overlaps the deferred xg2 stores
            if (!role && t + 1 < T_) {
                const uint4* src = (const uint4*)(xtb + ((size_t)(t + 1) * B_ + gb0) * XPW_);
#pragma unroll
                for (int i = 0; i < 10; ++i) {
                    int lin = tid + 256 * i;
                    int row = lin / 20, rem = lin - row * 20;
                    cpasync16(xt_su32 + (row * 88 + rem * 4) * 4, src + row * 20 + rem);
                }
                asm volatile("cp.async.commit_group;" ::: "memory");
            }

            // deferred xg2 STORES only (xac already computed with reused A)
            if (!role && t > 0) {
#pragma unroll
                for (int mf = 0; mf < 2; ++mf) {
                    float* xo = xg2 + ((size_t)(t - 1) * B_ + rowM + mf * 16) * G_;
                    __stcg((float2*)(xo + nc0),          make_float2(xac[mf][0][0] + bf00, xac[mf][0][1] + bf01));
                    __stcg((float2*)(xo + nc1),          make_float2(xac[mf][1][0] + bf10, xac[mf][1][1] + bf11));
                    __stcg((float2*)(xo + 8 * G_ + nc0), make_float2(xac[mf][0][2] + bf00, xac[mf][0][3] + bf01));
                    __stcg((float2*)(xo + 8 * G_ + nc1), make_float2(xac[mf][1][2] + bf10, xac[mf][1][3] + bf11));
                }
                __syncthreads();
                if (tid == 0) st_release_gpu(flag, (unsigned)t);
            }
        }
    }

    // ---- global drain barrier over all blocks, then replay-safe resets ----
    __syncthreads();
    if (tid == 0) {
        unsigned gen = *(volatile unsigned*)&g_gen;
        __threadfence();
        if (atomicAdd(&g_cnt, 1u) == gridDim.x - 1) {
            atomicExch(&g_cnt, 0u);
            __threadfence();
            atomicAdd(&g_gen, 1u);
        } else {
            while (*(volatile unsigned*)&g_gen == gen) { __nanosleep(64); }
        }
        if (!fcrole) {
            g_arr[barid][ublk] = 0u;
            if (isL2) *(volatile unsigned*)&g_l1prog[barid - 2][ublk] = 0u;
        }
    }
}

// ---------------- launch --------------------------------------------------------
extern "C" void kernel_launch(void* const* d_in, const int* in_sizes, int n_in,
                              void* d_out, int out_size)
{
    const float* x     = (const float*)d_in[0];
    const float* w_ih1 = (const float*)d_in[1];
    const float* w_hh1 = (const float*)d_in[2];
    const float* b_ih1 = (const float*)d_in[3];
    const float* b_hh1 = (const float*)d_in[4];
    const float* w_ih2 = (const float*)d_in[5];
    const float* w_hh2 = (const float*)d_in[6];
    const float* b_ih2 = (const float*)d_in[7];
    const float* b_hh2 = (const float*)d_in[8];
    const float* fc1_w = (const float*)d_in[9];
    const float* fc1_b = (const float*)d_in[10];
    const float* fc2_w = (const float*)d_in[11];
    const float* fc2_b = (const float*)d_in[12];
    float* out = (float*)d_out;

    float *xg2, *h2l, *wp2;
    unsigned *hs1, *hs2, *xtb;
    cudaGetSymbolAddress((void**)&xg2, g_xg2);
    cudaGetSymbolAddress((void**)&xtb, g_xtb);
    cudaGetSymbolAddress((void**)&hs1, g_hs1);
    cudaGetSymbolAddress((void**)&hs2, g_hs2);
    cudaGetSymbolAddress((void**)&h2l, g_h2l);
    cudaGetSymbolAddress((void**)&wp2, g_wp2);

    const int SMEM = SMEM_WORDS * 4;                 // 157696 B
    cudaFuncSetAttribute(lstm_fused, cudaFuncAttributeMaxDynamicSharedMemorySize, SMEM);

    // 0. pad fc2_w to [129,160]
    pad_w<<<(I_ * KP_ + 255) / 256, 256>>>(fc2_w, wp2, I_, I_);
    // 1. x -> packed bf16 xtb (fused transpose + pack)
    transpose_pack<<<dim3((T_ + 31) / 32, KP_ / 32, B_), dim3(32, 8)>>>(x, xtb);
    // 2. everything else: L1 + L2 waves + streaming FC, one persistent kernel
    lstm_fused<<<148, 256, SMEM>>>(xtb, w_ih1, b_ih1, b_hh1, w_hh1,
                                   w_ih2, w_hh2, b_ih2, b_hh2,
                                   hs1, hs2, h2l, xg2,
                                   fc1_w, fc1_b, wp2, fc2_b, out);
}